// round 5
// baseline (speedup 1.0000x reference)
#include <cuda_runtime.h>
#include <math.h>

constexpr float LRF = 0.001f;

// Padded buffer sizes
constexpr int NY0 = 4 * 128 * 34 * 34;   // y0 padded (pad 1)
constexpr int NRP = 4 * 64 * 36 * 36;    // r-space padded (pad 2)
constexpr int NDOTCTA = 128;

__device__ float g_y0[NY0];
__device__ float g_r0[NRP];
__device__ float g_m1[NRP];
__device__ float g_m2[NRP];
__device__ float g_m3[NRP];
__device__ float g_s[NRP];
__device__ float g_T[64 * 64 * 25];
__device__ double g_part[NDOTCTA * 10];
__device__ float g_w[4];

// ---------------------------------------------------------------------------
// Zero padded scratch buffers (borders must be 0).
// ---------------------------------------------------------------------------
__global__ __launch_bounds__(256) void zero_all()
{
    int i = blockIdx.x * blockDim.x + threadIdx.x;
    int stride = gridDim.x * blockDim.x;
    for (int j = i; j < NY0; j += stride) g_y0[j] = 0.f;
    for (int j = i; j < NRP; j += stride) {
        g_r0[j] = 0.f; g_m1[j] = 0.f; g_m2[j] = 0.f; g_m3[j] = 0.f;
    }
}

// ---------------------------------------------------------------------------
// Smem-staged 3x3 conv (cross-correlation), logical 32x32 output.
// Block 256 threads: col(32) x strip(NSTRIP, 4 rows each) x ocg(NOCG, OCB ch).
// Grid: (OC/OCB_TOT, 4, 32/RB).
// WM: 0 wgt[og][ic][u][v]; 1 wgt[ic][og][u][v]; 2 wgt[og][ic][2-u][2-v]
// EPI: 1 relu; 2 x - acc; 3 y0pad + acc + 1x1(x,wb)
// BOUNDS: input is raw x (32x32, predicated); else padded buffer (IPAD>=1).
// ---------------------------------------------------------------------------
template<int IC, int OC, int OCB_TOT, int RB, int IIH, int IIW, int IPAD,
         int WM, int EPI, int OPAD, int OPH, int OPW, bool BOUNDS>
__global__ __launch_bounds__(256)
void conv3s(const float* __restrict__ in, const float* __restrict__ wgt,
            const float* __restrict__ aux, const float* __restrict__ aux2,
            const float* __restrict__ wb, float* __restrict__ out)
{
    constexpr int NSTRIP = RB / 4;
    constexpr int NOCG   = 256 / (32 * NSTRIP);
    constexpr int OCB    = OCB_TOT / NOCG;
    constexpr int CH     = 8;
    constexpr int SROWS  = RB + 2;
    constexpr int SCOLS  = 34;

    __shared__ float wsm[IC * 9 * OCB_TOT];
    __shared__ float sin_s[CH * SROWS * SCOLS];
    __shared__ float wbs[(EPI == 3) ? 64 * OCB_TOT : 1];

    const int ocblk   = blockIdx.x;
    const int n       = blockIdx.y;
    const int rowbase = blockIdx.z * RB;
    const int tid     = threadIdx.x;

    for (int idx = tid; idx < OCB_TOT * IC * 9; idx += 256) {
        int o   = idx % OCB_TOT;
        int tap = (idx / OCB_TOT) % 9;
        int ic  = idx / (9 * OCB_TOT);
        int u = tap / 3, v = tap % 3;
        int og = ocblk * OCB_TOT + o;
        int src;
        if (WM == 0)      src = ((og * IC + ic) * 3 + u) * 3 + v;
        else if (WM == 1) src = ((ic * OC + og) * 3 + u) * 3 + v;
        else              src = ((og * IC + ic) * 3 + (2 - u)) * 3 + (2 - v);
        wsm[idx] = __ldg(wgt + src);
    }
    if (EPI == 3) {
        for (int idx = tid; idx < 64 * OCB_TOT; idx += 256) {
            int o = idx % OCB_TOT, c = idx / OCB_TOT;
            wbs[idx] = __ldg(wb + (ocblk * OCB_TOT + o) * 64 + c);
        }
    }

    const int col   = tid & 31;
    const int strip = (tid >> 5) % NSTRIP;
    const int ocg   = tid / (32 * NSTRIP);

    float acc[OCB][4];
    #pragma unroll
    for (int o = 0; o < OCB; o++)
        #pragma unroll
        for (int k = 0; k < 4; k++) acc[o][k] = 0.f;

    for (int chunk = 0; chunk < IC / CH; chunk++) {
        __syncthreads();
        const float* inb = in + ((size_t)n * IC + chunk * CH) * IIH * IIW;
        for (int idx = tid; idx < CH * SROWS * SCOLS; idx += 256) {
            int cc = idx % SCOLS;
            int rr = (idx / SCOLS) % SROWS;
            int c  = idx / (SCOLS * SROWS);
            int lr = rowbase - 1 + rr;
            int lc = cc - 1;
            float v;
            if (BOUNDS)
                v = (lr >= 0 && lr < 32 && lc >= 0 && lc < 32)
                        ? __ldg(inb + (size_t)c * IIH * IIW + lr * IIW + lc) : 0.f;
            else
                v = __ldg(inb + (size_t)c * IIH * IIW + (lr + IPAD) * IIW + (lc + IPAD));
            sin_s[idx] = v;
        }
        __syncthreads();

        #pragma unroll
        for (int c = 0; c < CH; c++) {
            const int ic = chunk * CH + c;
            float v[6][3];
            const float* sp = &sin_s[(c * SROWS + strip * 4) * SCOLS + col];
            #pragma unroll
            for (int rr = 0; rr < 6; rr++)
                #pragma unroll
                for (int cc = 0; cc < 3; cc++)
                    v[rr][cc] = sp[rr * SCOLS + cc];
            #pragma unroll
            for (int u = 0; u < 3; u++)
                #pragma unroll
                for (int vv = 0; vv < 3; vv++) {
                    const float* wp = &wsm[(ic * 9 + u * 3 + vv) * OCB_TOT + ocg * OCB];
                    #pragma unroll
                    for (int o = 0; o < OCB; o++) {
                        float wv = wp[o];
                        #pragma unroll
                        for (int k = 0; k < 4; k++)
                            acc[o][k] += v[u + k][vv] * wv;
                    }
                }
        }
    }

    // 1x1 bypass (EPI 3)
    float bp[OCB][4];
    if (EPI == 3) {
        #pragma unroll
        for (int o = 0; o < OCB; o++)
            #pragma unroll
            for (int k = 0; k < 4; k++) bp[o][k] = 0.f;
        const int row0 = rowbase + strip * 4;
        const float* xb = aux2 + ((size_t)n * 64 * 32 + row0) * 32 + col;
        #pragma unroll 4
        for (int c = 0; c < 64; c++) {
            float xv[4];
            #pragma unroll
            for (int k = 0; k < 4; k++) xv[k] = __ldg(xb + k * 32);
            #pragma unroll
            for (int o = 0; o < OCB; o++) {
                float wv = wbs[c * OCB_TOT + ocg * OCB + o];
                #pragma unroll
                for (int k = 0; k < 4; k++) bp[o][k] += xv[k] * wv;
            }
            xb += 32 * 32;
        }
    }

    const int row0 = rowbase + strip * 4;
    #pragma unroll
    for (int o = 0; o < OCB; o++) {
        int og = ocblk * OCB_TOT + ocg * OCB + o;
        #pragma unroll
        for (int k = 0; k < 4; k++) {
            int row = row0 + k;
            float val = acc[o][k];
            if (EPI == 1) val = fmaxf(val, 0.f);
            else if (EPI == 2)
                val = __ldg(aux + (((size_t)n * OC + og) * 32 + row) * 32 + col) - val;
            else if (EPI == 3)
                val = __ldg(aux + (((size_t)n * 128 + og) * 34 + row + 1) * 34 + col + 1)
                      + val + bp[o][k];
            out[(((size_t)n * OC + og) * OPH + row + OPAD) * OPW + col + OPAD] = val;
        }
    }
}

// ---------------------------------------------------------------------------
// Gram kernel: T[b][a][du+2][dv+2] = sum_o sum_{u,v} Wfb[o][b][u][v]*Wfb[o][a][u-du][v-dv]
// ---------------------------------------------------------------------------
__global__ __launch_bounds__(128)
void tgram_kernel(const float* __restrict__ Wfb, float* __restrict__ T)
{
    __shared__ float red[64 * 25];
    const int b    = blockIdx.x;
    const int a    = threadIdx.x & 63;
    const int half = threadIdx.x >> 6;

    float acc[25];
    #pragma unroll
    for (int t = 0; t < 25; t++) acc[t] = 0.f;

    for (int o = half * 64; o < half * 64 + 64; o++) {
        float wbv[9], wav[9];
        #pragma unroll
        for (int i = 0; i < 9; i++) {
            wbv[i] = __ldg(Wfb + (o * 64 + b) * 9 + i);
            wav[i] = __ldg(Wfb + (o * 64 + a) * 9 + i);
        }
        #pragma unroll
        for (int du = -2; du <= 2; du++)
            #pragma unroll
            for (int dv = -2; dv <= 2; dv++) {
                float s = 0.f;
                #pragma unroll
                for (int u = 0; u < 3; u++) {
                    if (u - du < 0 || u - du > 2) continue;
                    #pragma unroll
                    for (int v = 0; v < 3; v++) {
                        if (v - dv < 0 || v - dv > 2) continue;
                        s += wbv[u * 3 + v] * wav[(u - du) * 3 + (v - dv)];
                    }
                }
                acc[(du + 2) * 5 + (dv + 2)] += s;
            }
    }
    if (half == 1) {
        #pragma unroll
        for (int t = 0; t < 25; t++) red[a * 25 + t] = acc[t];
    }
    __syncthreads();
    if (half == 0) {
        #pragma unroll
        for (int t = 0; t < 25; t++)
            T[((size_t)b * 64 + a) * 25 + t] = acc[t] + red[a * 25 + t];
    }
}

// ---------------------------------------------------------------------------
// Smem-staged 5x5 conv in r-space (M = A A^T), 36x36 padded buffers, 64->64.
// Block 128 = col(32) x ocg(4); per-thread 1 ch x 4 rows.
// Grid: (16, 4, 8).
// ---------------------------------------------------------------------------
__global__ __launch_bounds__(128)
void conv5s(const float* __restrict__ in, const float* __restrict__ T,
            float* __restrict__ out)
{
    constexpr int OCB_TOT = 4;
    constexpr int CH = 8;

    __shared__ float wsm[64 * 25 * OCB_TOT];   // 25.6 KB
    __shared__ float sin_s[CH * 8 * 36];       // 9.2 KB

    const int ocblk   = blockIdx.x;
    const int n       = blockIdx.y;
    const int rowbase = blockIdx.z * 4;
    const int tid     = threadIdx.x;

    for (int idx = tid; idx < 64 * 25 * OCB_TOT; idx += 128) {
        int o   = idx % OCB_TOT;
        int tap = (idx / OCB_TOT) % 25;
        int a   = idx / (25 * OCB_TOT);
        wsm[idx] = __ldg(T + ((size_t)(ocblk * OCB_TOT + o) * 64 + a) * 25 + tap);
    }

    const int col = tid & 31;
    const int ocg = tid >> 5;

    float acc[4] = {0.f, 0.f, 0.f, 0.f};

    for (int chunk = 0; chunk < 64 / CH; chunk++) {
        __syncthreads();
        const float* inb = in + ((size_t)n * 64 + chunk * CH) * 36 * 36
                              + rowbase * 36;
        for (int idx = tid; idx < CH * 8 * 36; idx += 128) {
            int cc = idx % 36;
            int rr = (idx / 36) % 8;
            int c  = idx / (36 * 8);
            sin_s[idx] = __ldg(inb + (size_t)c * 36 * 36 + rr * 36 + cc);
        }
        __syncthreads();

        #pragma unroll
        for (int c = 0; c < CH; c++) {
            const int a = chunk * CH + c;
            float v[8][5];
            const float* sp = &sin_s[c * 8 * 36 + col];
            #pragma unroll
            for (int rr = 0; rr < 8; rr++)
                #pragma unroll
                for (int cc = 0; cc < 5; cc++)
                    v[rr][cc] = sp[rr * 36 + cc];
            #pragma unroll
            for (int du = 0; du < 5; du++)
                #pragma unroll
                for (int dv = 0; dv < 5; dv++) {
                    float wv = wsm[(a * 25 + du * 5 + dv) * OCB_TOT + ocg];
                    #pragma unroll
                    for (int k = 0; k < 4; k++)
                        acc[k] += v[k + du][dv] * wv;
                }
        }
    }

    const int og = ocblk * OCB_TOT + ocg;
    #pragma unroll
    for (int k = 0; k < 4; k++)
        out[(((size_t)n * 64 + og) * 36 + rowbase + k + 2) * 36 + col + 2] = acc[k];
}

// ---------------------------------------------------------------------------
// 10 pairwise dot products (borders zero everywhere, safe to include).
// ---------------------------------------------------------------------------
__global__ __launch_bounds__(256)
void dots_kernel(const float* __restrict__ m0, const float* __restrict__ m1,
                 const float* __restrict__ m2, const float* __restrict__ m3,
                 double* __restrict__ partials)
{
    double loc[10];
    #pragma unroll
    for (int d = 0; d < 10; d++) loc[d] = 0.0;
    for (int i = blockIdx.x * blockDim.x + threadIdx.x; i < NRP;
         i += gridDim.x * blockDim.x) {
        double a = m0[i], b = m1[i], c = m2[i], d = m3[i];
        loc[0] += a * a; loc[1] += a * b; loc[2] += a * c; loc[3] += a * d;
        loc[4] += b * b; loc[5] += b * c; loc[6] += b * d;
        loc[7] += c * c; loc[8] += c * d; loc[9] += d * d;
    }
    __shared__ double sm[256];
    for (int d = 0; d < 10; d++) {
        sm[threadIdx.x] = loc[d];
        __syncthreads();
        for (int s = 128; s > 0; s >>= 1) {
            if (threadIdx.x < s) sm[threadIdx.x] += sm[threadIdx.x + s];
            __syncthreads();
        }
        if (threadIdx.x == 0) partials[blockIdx.x * 10 + d] = sm[0];
        __syncthreads();
    }
}

// ---------------------------------------------------------------------------
// Final reduce + 500-step scalar recursion in degree-3 Krylov basis.
// ---------------------------------------------------------------------------
__global__ void recur_kernel(const double* __restrict__ partials,
                             float* __restrict__ wout)
{
    __shared__ double dsh[10];
    int lane = threadIdx.x;
    if (lane < 10) {
        double s = 0.0;
        for (int b = 0; b < NDOTCTA; b++) s += partials[b * 10 + lane];
        dsh[lane] = s;
    }
    __syncthreads();
    if (lane != 0) return;

    const float H00 = (float)dsh[0], H01 = (float)dsh[1], H02 = (float)dsh[2];
    const float H03 = (float)dsh[3], H11 = (float)dsh[4], H12 = (float)dsh[5];
    const float H13 = (float)dsh[6], H22 = (float)dsh[7], H23 = (float)dsh[8];
    const float H33 = (float)dsh[9];

    float p1 = 0.f, p2 = 0.f, p3 = 0.f;
    float w0 = 0.f, w1 = 0.f, w2 = 0.f, w3 = 0.f;
    for (int t = 0; t < 500; t++) {
        float nsq = H00
            + 2.f * (p1 * H01 + p2 * H02 + p3 * H03)
            + p1 * (p1 * H11 + 2.f * (p2 * H12 + p3 * H13))
            + p2 * (p2 * H22 + 2.f * p3 * H23)
            + p3 * p3 * H33;
        float c = LRF * rsqrtf(nsq);
        w0 += c; w1 += c * p1; w2 += c * p2; w3 += c * p3;
        p3 -= c * p2;
        p2 -= c * p1;
        p1 -= c;
    }
    wout[0] = w0; wout[1] = w1; wout[2] = w2; wout[3] = w3;
}

__global__ __launch_bounds__(256)
void combine_kernel(const float* __restrict__ m0, const float* __restrict__ m1,
                    const float* __restrict__ m2, const float* __restrict__ m3,
                    const float* __restrict__ w, float* __restrict__ s)
{
    float w0 = __ldg(w), w1 = __ldg(w + 1), w2 = __ldg(w + 2), w3 = __ldg(w + 3);
    for (int i = blockIdx.x * blockDim.x + threadIdx.x; i < NRP;
         i += gridDim.x * blockDim.x)
        s[i] = w0 * m0[i] + w1 * m1[i] + w2 * m2[i] + w3 * m3[i];
}

extern "C" void kernel_launch(void* const* d_in, const int* in_sizes, int n_in,
                              void* d_out, int out_size)
{
    const float* x   = (const float*)d_in[0];
    const float* Wff = (const float*)d_in[1];
    const float* Wfb = (const float*)d_in[2];
    const float* Wbp = (const float*)d_in[3];
    float* out = (float*)d_out;

    float *y0, *r0, *m1, *m2, *m3, *s, *w, *T;
    double* part;
    cudaGetSymbolAddress((void**)&y0, g_y0);
    cudaGetSymbolAddress((void**)&r0, g_r0);
    cudaGetSymbolAddress((void**)&m1, g_m1);
    cudaGetSymbolAddress((void**)&m2, g_m2);
    cudaGetSymbolAddress((void**)&m3, g_m3);
    cudaGetSymbolAddress((void**)&s,  g_s);
    cudaGetSymbolAddress((void**)&w,  g_w);
    cudaGetSymbolAddress((void**)&T,  g_T);
    cudaGetSymbolAddress((void**)&part, g_part);

    zero_all<<<512, 256>>>();
    tgram_kernel<<<64, 128>>>(Wfb, T);

    // y0 = relu(conv3x3_pad1(x, W_ff)) -> padded (4,128,34,34)
    // IC=64, OC=128, OCB_TOT=8, RB=8 -> grid (16,4,4), 2048 warps
    conv3s<64, 128, 8, 8, 32, 32, 0, 0, 1, 1, 34, 34, true>
        <<<dim3(16, 4, 4), 256>>>(x, Wff, nullptr, nullptr, nullptr, y0);

    // r0 = x - A(pad(y0)) -> padded (4,64,36,36)
    // IC=128, OC=64, OCB_TOT=4, RB=8 -> grid (16,4,4), 2048 warps
    conv3s<128, 64, 4, 8, 34, 34, 1, 1, 2, 2, 36, 36, false>
        <<<dim3(16, 4, 4), 256>>>(y0, Wfb, x, nullptr, nullptr, r0);

    // m_{i+1} = M m_i via 5x5 conv, grid (16,4,8) = 512 CTAs x 4 warps
    conv5s<<<dim3(16, 4, 8), 128>>>(r0, T, m1);
    conv5s<<<dim3(16, 4, 8), 128>>>(m1, T, m2);
    conv5s<<<dim3(16, 4, 8), 128>>>(m2, T, m3);

    dots_kernel<<<NDOTCTA, 256>>>(r0, m1, m2, m3, part);
    recur_kernel<<<1, 32>>>(part, w);
    combine_kernel<<<256, 256>>>(r0, m1, m2, m3, w, s);

    // out = y0 + crop(A^T s) + conv1x1(x, W_bypass)
    // IC=64, OC=128, OCB_TOT=8, RB=8 -> grid (16,4,4)
    conv3s<64, 128, 8, 8, 36, 36, 2, 2, 3, 0, 32, 32, false>
        <<<dim3(16, 4, 4), 256>>>(s, Wfb, y0, x, Wbp, out);
}

// round 7
// speedup vs baseline: 2.8333x; 2.8333x over previous
#include <cuda_runtime.h>
#include <math.h>

constexpr float LRF = 0.001f;

// All intermediate feature maps stored 36x36 with logical origin at (2,2);
// borders are zero. y0 needs halo +-1, r-space needs +-2 -- both fit.
constexpr int NY36 = 4 * 128 * 36 * 36;
constexpr int NRP  = 4 * 64 * 36 * 36;
constexpr int NDOTCTA = 128;

__device__ float g_y0[NY36];
__device__ float g_r0[NRP];
__device__ float g_m1[NRP];
__device__ float g_T[64 * 25 * 64];      // layout [(a*25+tap)*64 + b]
__device__ double g_part[NDOTCTA * 3];
__device__ float g_w[2];

// ---------------------------------------------------------------------------
// Zero padded scratch buffers (borders must be 0; interiors get overwritten).
// ---------------------------------------------------------------------------
__global__ __launch_bounds__(256) void zero_all()
{
    int i = blockIdx.x * blockDim.x + threadIdx.x;
    int stride = gridDim.x * blockDim.x;
    for (int j = i; j < NY36; j += stride) g_y0[j] = 0.f;
    for (int j = i; j < NRP; j += stride) { g_r0[j] = 0.f; g_m1[j] = 0.f; }
}

// ---------------------------------------------------------------------------
// Unified smem-staged 3x3 conv, logical 32x32 output.
// Block 256 = col(32) x strip(2; 4 rows each) x ocg(4; OCB oc each).
// CTA output: 8 rows x (4*OCB) oc.  Grid (OC/(4*OCB), 4, 4).
// Padded inputs (36-wide, origin(2,2)) staged via float4; raw x via predicated
// scalar loads.  Smem column m <-> logical column m-2; staged row rr <->
// logical row rowbase+rr-1.
// WM: 0 wgt[og][ic]; 1 wgt[ic][og]; 2 wgt[og][ic] spatially flipped.
// EPI: 1 relu -> padded out; 2 x - acc -> padded out;
//      3 (staged input = w0*in + w1*in2) y0 + acc + 1x1(x,wb) -> raw out.
// ---------------------------------------------------------------------------
template<int IC, int OC, int OCB, int WM, int EPI, bool BOUNDS>
__global__ __launch_bounds__(256)
void conv3k(const float* __restrict__ in, const float* __restrict__ in2,
            const float* __restrict__ wgt, const float* __restrict__ aux,
            const float* __restrict__ aux2, const float* __restrict__ wb,
            const float* __restrict__ gw, float* __restrict__ out)
{
    constexpr int OCTOT = 4 * OCB;
    constexpr int CH    = 16;

    __shared__ float wsm[CH * 9 * OCTOT];
    __shared__ float sin_s[CH * 10 * 36];
    __shared__ float wbs[(EPI == 3) ? 64 * OCTOT : 1];

    const int ocblk   = blockIdx.x;
    const int n       = blockIdx.y;
    const int rowbase = blockIdx.z * 8;
    const int tid     = threadIdx.x;
    const int col     = tid & 31;
    const int strip   = (tid >> 5) & 1;
    const int ocg     = tid >> 6;

    float w0 = 0.f, w1 = 0.f;
    if constexpr (EPI == 3) {
        w0 = __ldg(gw); w1 = __ldg(gw + 1);
        for (int idx = tid; idx < 64 * OCTOT; idx += 256) {
            int o = idx & (OCTOT - 1), c = idx / OCTOT;
            wbs[idx] = __ldg(wb + (ocblk * OCTOT + o) * 64 + c);
        }
    }

    float acc[OCB][4];
    #pragma unroll
    for (int o = 0; o < OCB; o++)
        #pragma unroll
        for (int k = 0; k < 4; k++) acc[o][k] = 0.f;

    for (int chunk = 0; chunk < IC / CH; chunk++) {
        __syncthreads();
        // Stage weight tile for this chunk: wsm[icl][tap][o]
        for (int idx = tid; idx < CH * 9 * OCTOT; idx += 256) {
            int o   = idx & (OCTOT - 1);
            int tap = (idx / OCTOT) % 9;
            int icl = idx / (9 * OCTOT);
            int ic  = chunk * CH + icl;
            int u = tap / 3, v = tap % 3;
            int og = ocblk * OCTOT + o;
            int src;
            if (WM == 0)      src = ((og * IC + ic) * 3 + u) * 3 + v;
            else if (WM == 1) src = ((ic * OC + og) * 3 + u) * 3 + v;
            else              src = ((og * IC + ic) * 3 + (2 - u)) * 3 + (2 - v);
            wsm[idx] = __ldg(wgt + src);
        }
        // Stage input tile
        if constexpr (BOUNDS) {
            const float* inb = in + ((size_t)n * IC + chunk * CH) * 1024;
            for (int idx = tid; idx < CH * 10 * 36; idx += 256) {
                int cc = idx % 36;
                int rr = (idx / 36) % 10;
                int c  = idx / 360;
                int lr = rowbase + rr - 1, lc = cc - 2;
                sin_s[idx] = (lr >= 0 && lr < 32 && lc >= 0 && lc < 32)
                                 ? __ldg(inb + c * 1024 + lr * 32 + lc) : 0.f;
            }
        } else {
            const float4* in4  = (const float4*)in;
            const float4* in24 = (const float4*)in2;
            for (int idx = tid; idx < CH * 10 * 9; idx += 256) {
                int cc4 = idx % 9;
                int rr  = (idx / 9) % 10;
                int c   = idx / 90;
                size_t g = (((size_t)n * IC + chunk * CH + c) * 36
                            + rowbase + 1 + rr) * 9 + cc4;
                float4 v = __ldg(in4 + g);
                if constexpr (EPI == 3) {
                    float4 v2 = __ldg(in24 + g);
                    v.x = w0 * v.x + w1 * v2.x;
                    v.y = w0 * v.y + w1 * v2.y;
                    v.z = w0 * v.z + w1 * v2.z;
                    v.w = w0 * v.w + w1 * v2.w;
                }
                ((float4*)sin_s)[idx] = v;
            }
        }
        __syncthreads();

        #pragma unroll
        for (int c = 0; c < CH; c++) {
            float v[6][3];
            const float* sp = &sin_s[(c * 10 + strip * 4) * 36 + col + 1];
            #pragma unroll
            for (int rr = 0; rr < 6; rr++)
                #pragma unroll
                for (int cc = 0; cc < 3; cc++)
                    v[rr][cc] = sp[rr * 36 + cc];
            #pragma unroll
            for (int tap = 0; tap < 9; tap++) {
                int u = tap / 3, vv = tap % 3;
                const float* wp = &wsm[(c * 9 + tap) * OCTOT + ocg * OCB];
                if constexpr (OCB == 4) {
                    float4 wv = *(const float4*)wp;
                    float wa[4] = {wv.x, wv.y, wv.z, wv.w};
                    #pragma unroll
                    for (int o = 0; o < 4; o++)
                        #pragma unroll
                        for (int k = 0; k < 4; k++)
                            acc[o][k] += v[u + k][vv] * wa[o];
                } else if constexpr (OCB == 2) {
                    float2 wv = *(const float2*)wp;
                    #pragma unroll
                    for (int k = 0; k < 4; k++) {
                        acc[0][k] += v[u + k][vv] * wv.x;
                        acc[1][k] += v[u + k][vv] * wv.y;
                    }
                } else {
                    float wv = wp[0];
                    #pragma unroll
                    for (int k = 0; k < 4; k++)
                        acc[0][k] += v[u + k][vv] * wv;
                }
            }
        }
    }

    const int row0 = rowbase + strip * 4;

    // 1x1 bypass (EPI 3)
    float bp[OCB][4];
    if constexpr (EPI == 3) {
        #pragma unroll
        for (int o = 0; o < OCB; o++)
            #pragma unroll
            for (int k = 0; k < 4; k++) bp[o][k] = 0.f;
        const float* xb = aux2 + ((size_t)n * 64 * 32 + row0) * 32 + col;
        #pragma unroll 4
        for (int c = 0; c < 64; c++) {
            float xv[4];
            #pragma unroll
            for (int k = 0; k < 4; k++) xv[k] = __ldg(xb + k * 32);
            #pragma unroll
            for (int o = 0; o < OCB; o++) {
                float wv = wbs[c * OCTOT + ocg * OCB + o];
                #pragma unroll
                for (int k = 0; k < 4; k++) bp[o][k] += xv[k] * wv;
            }
            xb += 32 * 32;
        }
    }

    #pragma unroll
    for (int o = 0; o < OCB; o++) {
        int og = ocblk * OCTOT + ocg * OCB + o;
        #pragma unroll
        for (int k = 0; k < 4; k++) {
            int row = row0 + k;
            float val = acc[o][k];
            if constexpr (EPI == 1) {
                val = fmaxf(val, 0.f);
                out[((size_t)(n * OC + og) * 36 + row + 2) * 36 + col + 2] = val;
            } else if constexpr (EPI == 2) {
                val = __ldg(aux + ((size_t)(n * OC + og) * 32 + row) * 32 + col) - val;
                out[((size_t)(n * OC + og) * 36 + row + 2) * 36 + col + 2] = val;
            } else {
                val = __ldg(aux + ((size_t)(n * 128 + og) * 36 + row + 2) * 36 + col + 2)
                      + val + bp[o][k];
                out[((size_t)(n * OC + og) * 32 + row) * 32 + col] = val;
            }
        }
    }
}

// ---------------------------------------------------------------------------
// Gram kernel: for out-channel b, in-channel a, 25 taps:
//   T[(a*25+tap)*64+b] = sum_o sum_{u,v} Wfb[o][b][u][v]*Wfb[o][a][u-du][v-dv]
// ---------------------------------------------------------------------------
__global__ __launch_bounds__(128)
void tgram_kernel(const float* __restrict__ Wfb, float* __restrict__ T)
{
    __shared__ float red[64 * 25];
    const int b    = blockIdx.x;
    const int a    = threadIdx.x & 63;
    const int half = threadIdx.x >> 6;

    float acc[25];
    #pragma unroll
    for (int t = 0; t < 25; t++) acc[t] = 0.f;

    for (int o = half * 64; o < half * 64 + 64; o++) {
        float wbv[9], wav[9];
        #pragma unroll
        for (int i = 0; i < 9; i++) {
            wbv[i] = __ldg(Wfb + (o * 64 + b) * 9 + i);
            wav[i] = __ldg(Wfb + (o * 64 + a) * 9 + i);
        }
        #pragma unroll
        for (int du = -2; du <= 2; du++)
            #pragma unroll
            for (int dv = -2; dv <= 2; dv++) {
                float s = 0.f;
                #pragma unroll
                for (int u = 0; u < 3; u++) {
                    if (u - du < 0 || u - du > 2) continue;
                    #pragma unroll
                    for (int v = 0; v < 3; v++) {
                        if (v - dv < 0 || v - dv > 2) continue;
                        s += wbv[u * 3 + v] * wav[(u - du) * 3 + (v - dv)];
                    }
                }
                acc[(du + 2) * 5 + (dv + 2)] += s;
            }
    }
    if (half == 1) {
        #pragma unroll
        for (int t = 0; t < 25; t++) red[a * 25 + t] = acc[t];
    }
    __syncthreads();
    if (half == 0) {
        #pragma unroll
        for (int t = 0; t < 25; t++)
            T[((size_t)a * 25 + t) * 64 + b] = acc[t] + red[a * 25 + t];
    }
}

// ---------------------------------------------------------------------------
// 5x5 Gram conv (M = A A^T) in 64-channel r-space, 36-wide padded buffers.
// Block 256 = col(32) x ocg(8), OCB=2 -> CTA = 16 oc x 4 rows.
// Grid (4, 4, 8).  Per-chunk weight tile wsm[al][tap][o16] (coalesced).
// ---------------------------------------------------------------------------
__global__ __launch_bounds__(256)
void conv5k(const float* __restrict__ in, const float* __restrict__ T,
            float* __restrict__ out)
{
    __shared__ float wsm[16 * 25 * 16];   // 25.6 KB
    __shared__ float sin_s[16 * 8 * 36];  // 18.4 KB

    const int ocblk = blockIdx.x;
    const int n     = blockIdx.y;
    const int R0    = blockIdx.z * 4;     // logical out rows R0..R0+3
    const int tid   = threadIdx.x;
    const int col   = tid & 31;
    const int ocg   = tid >> 5;

    float acc[2][4];
    #pragma unroll
    for (int o = 0; o < 2; o++)
        #pragma unroll
        for (int k = 0; k < 4; k++) acc[o][k] = 0.f;

    for (int chunk = 0; chunk < 4; chunk++) {
        __syncthreads();
        const int a0 = chunk * 16;
        for (int idx = tid; idx < 6400; idx += 256) {
            int o   = idx & 15;
            int r2  = idx >> 4;
            int tap = r2 % 25;
            int al  = r2 / 25;
            wsm[idx] = __ldg(T + ((size_t)(a0 + al) * 25 + tap) * 64
                               + ocblk * 16 + o);
        }
        const float4* in4 = (const float4*)in;
        for (int idx = tid; idx < 1152; idx += 256) {
            int cc4 = idx % 9;
            int rr  = (idx / 9) % 8;
            int c   = idx / 72;
            ((float4*)sin_s)[idx] =
                __ldg(in4 + (((size_t)n * 64 + a0 + c) * 36 + R0 + rr) * 9 + cc4);
        }
        __syncthreads();

        #pragma unroll
        for (int c = 0; c < 16; c++) {
            float v[8][5];
            const float* sp = &sin_s[c * 288 + col];
            #pragma unroll
            for (int rr = 0; rr < 8; rr++)
                #pragma unroll
                for (int dv = 0; dv < 5; dv++)
                    v[rr][dv] = sp[rr * 36 + dv];
            #pragma unroll
            for (int tap = 0; tap < 25; tap++) {
                int du = tap / 5, dv = tap % 5;
                float2 wv = *(const float2*)&wsm[(c * 25 + tap) * 16 + ocg * 2];
                #pragma unroll
                for (int k = 0; k < 4; k++) {
                    acc[0][k] += v[k + du][dv] * wv.x;
                    acc[1][k] += v[k + du][dv] * wv.y;
                }
            }
        }
    }

    #pragma unroll
    for (int o = 0; o < 2; o++) {
        int og = ocblk * 16 + ocg * 2 + o;
        #pragma unroll
        for (int k = 0; k < 4; k++)
            out[((size_t)(n * 64 + og) * 36 + R0 + k + 2) * 36 + col + 2] = acc[o][k];
    }
}

// ---------------------------------------------------------------------------
// 3 dot products: <r0,r0>, <r0,m1>, <m1,m1> (borders zero -> safe to include).
// ---------------------------------------------------------------------------
__global__ __launch_bounds__(256)
void dots_kernel(const float* __restrict__ m0, const float* __restrict__ m1,
                 double* __restrict__ partials)
{
    double l0 = 0.0, l1 = 0.0, l2 = 0.0;
    for (int i = blockIdx.x * blockDim.x + threadIdx.x; i < NRP;
         i += gridDim.x * blockDim.x) {
        double a = m0[i], b = m1[i];
        l0 += a * a; l1 += a * b; l2 += b * b;
    }
    __shared__ double sm[256];
    double loc[3] = {l0, l1, l2};
    for (int d = 0; d < 3; d++) {
        sm[threadIdx.x] = loc[d];
        __syncthreads();
        for (int s = 128; s > 0; s >>= 1) {
            if (threadIdx.x < s) sm[threadIdx.x] += sm[threadIdx.x + s];
            __syncthreads();
        }
        if (threadIdx.x == 0) partials[blockIdx.x * 3 + d] = sm[0];
        __syncthreads();
    }
}

// ---------------------------------------------------------------------------
// Final reduce + 500-step scalar recursion in degree-1 Krylov basis.
// ---------------------------------------------------------------------------
__global__ void recur_kernel(const double* __restrict__ partials,
                             float* __restrict__ wout)
{
    __shared__ double dsh[3];
    int lane = threadIdx.x;
    if (lane < 3) {
        double s = 0.0;
        for (int b = 0; b < NDOTCTA; b++) s += partials[b * 3 + lane];
        dsh[lane] = s;
    }
    __syncthreads();
    if (lane != 0) return;

    const float H00 = (float)dsh[0], H01 = (float)dsh[1], H11 = (float)dsh[2];
    float p1 = 0.f, w0 = 0.f, w1 = 0.f;
    for (int t = 0; t < 500; t++) {
        float nsq = H00 + p1 * (2.f * H01 + p1 * H11);
        float c = LRF * rsqrtf(nsq);
        w0 += c; w1 += c * p1;
        p1 -= c;
    }
    wout[0] = w0; wout[1] = w1;
}

extern "C" void kernel_launch(void* const* d_in, const int* in_sizes, int n_in,
                              void* d_out, int out_size)
{
    const float* x   = (const float*)d_in[0];
    const float* Wff = (const float*)d_in[1];
    const float* Wfb = (const float*)d_in[2];
    const float* Wbp = (const float*)d_in[3];
    float* out = (float*)d_out;

    float *y0, *r0, *m1, *w, *T;
    double* part;
    cudaGetSymbolAddress((void**)&y0, g_y0);
    cudaGetSymbolAddress((void**)&r0, g_r0);
    cudaGetSymbolAddress((void**)&m1, g_m1);
    cudaGetSymbolAddress((void**)&w,  g_w);
    cudaGetSymbolAddress((void**)&T,  g_T);
    cudaGetSymbolAddress((void**)&part, g_part);

    zero_all<<<256, 256>>>();
    tgram_kernel<<<64, 128>>>(Wfb, T);

    // y0 = relu(conv3x3_pad1(x, W_ff)) -> padded (4,128,36,36) origin(2,2)
    conv3k<64, 128, 4, 0, 1, true>
        <<<dim3(8, 4, 4), 256>>>(x, nullptr, Wff, nullptr, nullptr, nullptr,
                                 nullptr, y0);

    // r0 = x - A(pad(y0)) -> padded (4,64,36,36)
    conv3k<128, 64, 2, 1, 2, false>
        <<<dim3(8, 4, 4), 256>>>(y0, nullptr, Wfb, x, nullptr, nullptr,
                                 nullptr, r0);

    // m1 = M r0 via single 5x5 Gram conv
    conv5k<<<dim3(4, 4, 8), 256>>>(r0, T, m1);

    // 2x2 Gram of Krylov basis, scalar 500-step recursion
    dots_kernel<<<NDOTCTA, 256>>>(r0, m1, part);
    recur_kernel<<<1, 32>>>(part, w);

    // out = y0 + crop(A^T (w0*r0 + w1*m1)) + conv1x1(x, W_bypass)
    // (combine fused into input staging of the final conv)
    conv3k<64, 128, 4, 2, 3, false>
        <<<dim3(8, 4, 4), 256>>>(r0, m1, Wfb, y0, x, Wbp, w, out);
}

// round 8
// speedup vs baseline: 3.2733x; 1.1553x over previous
#include <cuda_runtime.h>
#include <math.h>
#include <stdint.h>

constexpr float LRF = 0.001f;

// All feature maps stored 36x36 with logical origin (2,2); borders zero.
constexpr int NY36 = 4 * 128 * 36 * 36;
constexpr int NRP  = 4 * 64 * 36 * 36;
constexpr int NDOTCTA = 128;

__device__ __align__(16) float g_x36[NRP];
__device__ __align__(16) float g_y0[NY36];
__device__ __align__(16) float g_r0[NRP];
__device__ __align__(16) float g_m1[NRP];
__device__ __align__(16) float g_s[NRP];
__device__ __align__(16) float g_T[64 * 25 * 64];     // [(a*25+tap)*64 + b]
__device__ __align__(16) float g_WffP[64 * 9 * 128];  // [(ic*9+tap)*128 + oc]
__device__ __align__(16) float g_WfbP1[128 * 9 * 64]; // [(ic*9+tap)*64  + oc]
__device__ __align__(16) float g_WfbP2[64 * 9 * 128]; // [(ic*9+tap)*128 + og], flipped
__device__ double g_part[NDOTCTA * 3];
__device__ float g_w[2];

// ---------------- cp.async helpers ----------------
__device__ __forceinline__ void cpa16(uint32_t d, const void* s) {
    asm volatile("cp.async.cg.shared.global [%0], [%1], 16;" :: "r"(d), "l"(s));
}
__device__ __forceinline__ void cpcommit() { asm volatile("cp.async.commit_group;"); }
__device__ __forceinline__ void cpwait1()  { asm volatile("cp.async.wait_group 1;"); }
__device__ __forceinline__ void cpwait0()  { asm volatile("cp.async.wait_group 0;"); }

// ---------------------------------------------------------------------------
// prep: pad x into 36-wide layout; zero buffers whose borders must be zero.
// ---------------------------------------------------------------------------
__global__ __launch_bounds__(256) void prep_kernel(const float* __restrict__ x)
{
    int i = blockIdx.x * blockDim.x + threadIdx.x;
    int stride = gridDim.x * blockDim.x;
    for (int j = i; j < NRP; j += stride) {
        int c36 = j % 36;
        int r36 = (j / 36) % 36;
        int nc  = j / 1296;
        float v = 0.f;
        if (r36 >= 2 && r36 < 34 && c36 >= 2 && c36 < 34)
            v = __ldg(x + nc * 1024 + (r36 - 2) * 32 + (c36 - 2));
        g_x36[j] = v;
        g_r0[j] = 0.f;
        g_m1[j] = 0.f;
    }
    for (int j = i; j < NY36; j += stride) g_y0[j] = 0.f;
}

// ---------------------------------------------------------------------------
// wprep: re-lay weights into [ic][tap][oc] (final conv's spatially flipped).
// ---------------------------------------------------------------------------
__global__ __launch_bounds__(256)
void wprep_kernel(const float* __restrict__ Wff, const float* __restrict__ Wfb)
{
    int i = blockIdx.x * blockDim.x + threadIdx.x;
    int stride = gridDim.x * blockDim.x;
    for (int j = i; j < 73728; j += stride) {
        int oc  = j % 128;
        int tap = (j / 128) % 9;
        int ic  = j / 1152;
        g_WffP[j]  = __ldg(Wff + (oc * 64 + ic) * 9 + tap);
        g_WfbP2[j] = __ldg(Wfb + (oc * 64 + ic) * 9 + (8 - tap));
    }
    for (int j = i; j < 73728; j += stride) {
        int oc  = j % 64;
        int tap = (j / 64) % 9;
        int ic  = j / 576;
        g_WfbP1[j] = __ldg(Wfb + (ic * 64 + oc) * 9 + tap);
    }
}

// ---------------------------------------------------------------------------
// tgram: T[(a*25+tap)*64+b] = sum_o sum_{uv} Wfb[o][b][u][v]*Wfb[o][a][u-du][v-dv]
// ---------------------------------------------------------------------------
__global__ __launch_bounds__(128)
void tgram_kernel(const float* __restrict__ Wfb, float* __restrict__ T)
{
    __shared__ float red[64 * 25];
    const int b    = blockIdx.x;
    const int a    = threadIdx.x & 63;
    const int half = threadIdx.x >> 6;

    float acc[25];
    #pragma unroll
    for (int t = 0; t < 25; t++) acc[t] = 0.f;

    for (int o = half * 64; o < half * 64 + 64; o++) {
        float wbv[9], wav[9];
        #pragma unroll
        for (int i = 0; i < 9; i++) {
            wbv[i] = __ldg(Wfb + (o * 64 + b) * 9 + i);
            wav[i] = __ldg(Wfb + (o * 64 + a) * 9 + i);
        }
        #pragma unroll
        for (int du = -2; du <= 2; du++)
            #pragma unroll
            for (int dv = -2; dv <= 2; dv++) {
                float s = 0.f;
                #pragma unroll
                for (int u = 0; u < 3; u++) {
                    if (u - du < 0 || u - du > 2) continue;
                    #pragma unroll
                    for (int v = 0; v < 3; v++) {
                        if (v - dv < 0 || v - dv > 2) continue;
                        s += wbv[u * 3 + v] * wav[(u - du) * 3 + (v - dv)];
                    }
                }
                acc[(du + 2) * 5 + (dv + 2)] += s;
            }
    }
    if (half == 1) {
        #pragma unroll
        for (int t = 0; t < 25; t++) red[a * 25 + t] = acc[t];
    }
    __syncthreads();
    if (half == 0) {
        #pragma unroll
        for (int t = 0; t < 25; t++)
            T[((size_t)a * 25 + t) * 64 + b] = acc[t] + red[a * 25 + t];
    }
}

// ---------------------------------------------------------------------------
// cp.async double-buffered 3x3 conv.  Block 128 = col(32) x ocg(4), OCB=2.
// CTA output: 4 rows x 8 oc.  Grid (OC/8, 4, 8).
// Input: 36-wide padded, origin (2,2); weights prepped [ic][tap][oc].
// EPI: 1 relu -> padded out; 2 x - acc -> padded out;
//      3 y0 + acc + 1x1(x, wb) -> raw 32x32 out.
// ---------------------------------------------------------------------------
template<int IC, int OC, int EPI>
__global__ __launch_bounds__(128)
void conv3a(const float* __restrict__ in, const float* __restrict__ wgtP,
            const float* __restrict__ aux, const float* __restrict__ aux2,
            const float* __restrict__ wb, float* __restrict__ out)
{
    constexpr int CH  = 16, NCH = IC / CH;
    constexpr int INF = CH * 6 * 36;   // 3456 floats
    constexpr int WF  = CH * 9 * 8;    // 1152 floats
    __shared__ __align__(16) float sbuf[2][INF + WF];
    __shared__ __align__(16) float wbs[(EPI == 3) ? 512 : 4];

    const int ocblk = blockIdx.x;
    const int n     = blockIdx.y;
    const int R0    = blockIdx.z * 4;
    const int tid   = threadIdx.x;
    const int col   = tid & 31;
    const int ocg   = tid >> 5;

    if constexpr (EPI == 3) {
        for (int idx = tid; idx < 512; idx += 128) {
            int o = idx & 7, c = idx >> 3;
            wbs[c * 8 + o] = __ldg(wb + (ocblk * 8 + o) * 64 + c);
        }
    }

    const float4* in4 = (const float4*)in;
    const float4* w4  = (const float4*)wgtP;

    auto stage = [&](int buf, int chunk) {
        uint32_t sb = (uint32_t)__cvta_generic_to_shared(&sbuf[buf][0]);
        #pragma unroll 1
        for (int idx = tid; idx < INF / 4; idx += 128) {
            int cc4 = idx % 9;
            int rr  = (idx / 9) % 6;
            int c   = idx / 54;
            cpa16(sb + idx * 16,
                  in4 + (((size_t)n * IC + chunk * CH + c) * 36 + R0 + 1 + rr) * 9 + cc4);
        }
        uint32_t wsb = sb + INF * 4;
        #pragma unroll 1
        for (int idx = tid; idx < WF / 4; idx += 128) {
            int f   = idx & 1;
            int tp  = (idx >> 1) % 9;
            int icl = idx / 18;
            cpa16(wsb + idx * 16,
                  w4 + ((((chunk * CH + icl) * 9 + tp) * OC + ocblk * 8) >> 2) + f);
        }
        cpcommit();
    };

    float acc[2][4] = {};

    stage(0, 0);
    for (int c = 0; c < NCH; c++) {
        if (c + 1 < NCH) { stage((c + 1) & 1, c + 1); cpwait1(); }
        else cpwait0();
        __syncthreads();
        const float* sb  = &sbuf[c & 1][0];
        const float* wsm = sb + INF;
        #pragma unroll
        for (int ch = 0; ch < CH; ch++) {
            float v[6][3];
            const float* sp = sb + ch * 216 + col + 1;
            #pragma unroll
            for (int rr = 0; rr < 6; rr++)
                #pragma unroll
                for (int cc = 0; cc < 3; cc++)
                    v[rr][cc] = sp[rr * 36 + cc];
            #pragma unroll
            for (int tap = 0; tap < 9; tap++) {
                int u = tap / 3, vv = tap % 3;
                float2 wv = *(const float2*)&wsm[(ch * 9 + tap) * 8 + ocg * 2];
                #pragma unroll
                for (int k = 0; k < 4; k++) {
                    acc[0][k] += v[u + k][vv] * wv.x;
                    acc[1][k] += v[u + k][vv] * wv.y;
                }
            }
        }
        __syncthreads();
    }

    float bp[2][4] = {};
    if constexpr (EPI == 3) {
        const float* xb = aux2 + ((size_t)n * 64 * 32 + R0) * 32 + col;
        #pragma unroll 4
        for (int c = 0; c < 64; c++) {
            float xv[4];
            #pragma unroll
            for (int k = 0; k < 4; k++) xv[k] = __ldg(xb + k * 32);
            float2 wv = *(const float2*)&wbs[c * 8 + ocg * 2];
            #pragma unroll
            for (int k = 0; k < 4; k++) {
                bp[0][k] += xv[k] * wv.x;
                bp[1][k] += xv[k] * wv.y;
            }
            xb += 1024;
        }
    }

    #pragma unroll
    for (int o = 0; o < 2; o++) {
        int og = ocblk * 8 + ocg * 2 + o;
        #pragma unroll
        for (int k = 0; k < 4; k++) {
            int row = R0 + k;
            float val = acc[o][k];
            if constexpr (EPI == 1) {
                val = fmaxf(val, 0.f);
                out[((size_t)(n * OC + og) * 36 + row + 2) * 36 + col + 2] = val;
            } else if constexpr (EPI == 2) {
                val = __ldg(aux + ((size_t)(n * OC + og) * 32 + row) * 32 + col) - val;
                out[((size_t)(n * OC + og) * 36 + row + 2) * 36 + col + 2] = val;
            } else {
                val = __ldg(aux + ((size_t)(n * 128 + og) * 36 + row + 2) * 36 + col + 2)
                      + val + bp[o][k];
                out[((size_t)(n * OC + og) * 32 + row) * 32 + col] = val;
            }
        }
    }
}

// ---------------------------------------------------------------------------
// cp.async double-buffered 5x5 Gram conv (M = A A^T), 64->64 channels.
// Block 128 = col(32) x ocg(4), OCB=2; CTA = 4 rows x 8 oc.  Grid (8,4,8).
// ---------------------------------------------------------------------------
__global__ __launch_bounds__(128)
void conv5a(const float* __restrict__ in, const float* __restrict__ T,
            float* __restrict__ out)
{
    constexpr int CH  = 8, NCH = 8;
    constexpr int INF = CH * 8 * 36;   // 2304 floats
    constexpr int WF  = CH * 25 * 8;   // 1600 floats
    __shared__ __align__(16) float sbuf[2][INF + WF];

    const int ocblk = blockIdx.x;
    const int n     = blockIdx.y;
    const int R0    = blockIdx.z * 4;
    const int tid   = threadIdx.x;
    const int col   = tid & 31;
    const int ocg   = tid >> 5;

    const float4* in4 = (const float4*)in;
    const float4* t4  = (const float4*)T;

    auto stage = [&](int buf, int chunk) {
        uint32_t sb = (uint32_t)__cvta_generic_to_shared(&sbuf[buf][0]);
        #pragma unroll 1
        for (int idx = tid; idx < INF / 4; idx += 128) {
            int cc4 = idx % 9;
            int rr  = (idx / 9) % 8;
            int c   = idx / 72;
            cpa16(sb + idx * 16,
                  in4 + (((size_t)n * 64 + chunk * CH + c) * 36 + R0 + rr) * 9 + cc4);
        }
        uint32_t wsb = sb + INF * 4;
        #pragma unroll 1
        for (int idx = tid; idx < WF / 4; idx += 128) {
            int f   = idx & 1;
            int tap = (idx >> 1) % 25;
            int al  = idx / 50;
            cpa16(wsb + idx * 16,
                  t4 + ((((chunk * CH + al) * 25 + tap) * 64 + ocblk * 8) >> 2) + f);
        }
        cpcommit();
    };

    float acc[2][4] = {};

    stage(0, 0);
    for (int c = 0; c < NCH; c++) {
        if (c + 1 < NCH) { stage((c + 1) & 1, c + 1); cpwait1(); }
        else cpwait0();
        __syncthreads();
        const float* sb  = &sbuf[c & 1][0];
        const float* wsm = sb + INF;
        #pragma unroll
        for (int ch = 0; ch < CH; ch++) {
            float v[8][5];
            const float* sp = sb + ch * 288 + col;
            #pragma unroll
            for (int rr = 0; rr < 8; rr++)
                #pragma unroll
                for (int dv = 0; dv < 5; dv++)
                    v[rr][dv] = sp[rr * 36 + dv];
            #pragma unroll
            for (int tap = 0; tap < 25; tap++) {
                int du = tap / 5, dv = tap % 5;
                float2 wv = *(const float2*)&wsm[(ch * 25 + tap) * 8 + ocg * 2];
                #pragma unroll
                for (int k = 0; k < 4; k++) {
                    acc[0][k] += v[k + du][dv] * wv.x;
                    acc[1][k] += v[k + du][dv] * wv.y;
                }
            }
        }
        __syncthreads();
    }

    #pragma unroll
    for (int o = 0; o < 2; o++) {
        int og = ocblk * 8 + ocg * 2 + o;
        #pragma unroll
        for (int k = 0; k < 4; k++)
            out[((size_t)(n * 64 + og) * 36 + R0 + k + 2) * 36 + col + 2] = acc[o][k];
    }
}

// ---------------------------------------------------------------------------
// 3 dot products: <r0,r0>, <r0,m1>, <m1,m1>.
// ---------------------------------------------------------------------------
__global__ __launch_bounds__(256)
void dots_kernel(const float* __restrict__ m0, const float* __restrict__ m1,
                 double* __restrict__ partials)
{
    double l0 = 0.0, l1 = 0.0, l2 = 0.0;
    for (int i = blockIdx.x * blockDim.x + threadIdx.x; i < NRP;
         i += gridDim.x * blockDim.x) {
        double a = m0[i], b = m1[i];
        l0 += a * a; l1 += a * b; l2 += b * b;
    }
    __shared__ double sm[256];
    double loc[3] = {l0, l1, l2};
    for (int d = 0; d < 3; d++) {
        sm[threadIdx.x] = loc[d];
        __syncthreads();
        for (int s = 128; s > 0; s >>= 1) {
            if (threadIdx.x < s) sm[threadIdx.x] += sm[threadIdx.x + s];
            __syncthreads();
        }
        if (threadIdx.x == 0) partials[blockIdx.x * 3 + d] = sm[0];
        __syncthreads();
    }
}

// ---------------------------------------------------------------------------
// Final reduce + 500-step scalar recursion in degree-1 Krylov basis.
// ---------------------------------------------------------------------------
__global__ void recur_kernel(const double* __restrict__ partials,
                             float* __restrict__ wout)
{
    __shared__ double dsh[3];
    int lane = threadIdx.x;
    if (lane < 3) {
        double s = 0.0;
        for (int b = 0; b < NDOTCTA; b++) s += partials[b * 3 + lane];
        dsh[lane] = s;
    }
    __syncthreads();
    if (lane != 0) return;

    const float H00 = (float)dsh[0], H01 = (float)dsh[1], H11 = (float)dsh[2];
    float p1 = 0.f, w0 = 0.f, w1 = 0.f;
    for (int t = 0; t < 500; t++) {
        float nsq = H00 + p1 * (2.f * H01 + p1 * H11);
        float c = LRF * rsqrtf(nsq);
        w0 += c; w1 += c * p1;
        p1 -= c;
    }
    wout[0] = w0; wout[1] = w1;
}

// s = w0*r0 + w1*m1 (float4; borders become 0 automatically)
__global__ __launch_bounds__(256)
void combine_kernel(const float* __restrict__ m0, const float* __restrict__ m1,
                    const float* __restrict__ w, float* __restrict__ s)
{
    float w0 = __ldg(w), w1 = __ldg(w + 1);
    const float4* a4 = (const float4*)m0;
    const float4* b4 = (const float4*)m1;
    float4* s4 = (float4*)s;
    for (int i = blockIdx.x * blockDim.x + threadIdx.x; i < NRP / 4;
         i += gridDim.x * blockDim.x) {
        float4 a = __ldg(a4 + i), b = __ldg(b4 + i);
        float4 r;
        r.x = w0 * a.x + w1 * b.x;
        r.y = w0 * a.y + w1 * b.y;
        r.z = w0 * a.z + w1 * b.z;
        r.w = w0 * a.w + w1 * b.w;
        s4[i] = r;
    }
}

extern "C" void kernel_launch(void* const* d_in, const int* in_sizes, int n_in,
                              void* d_out, int out_size)
{
    const float* x   = (const float*)d_in[0];
    const float* Wff = (const float*)d_in[1];
    const float* Wfb = (const float*)d_in[2];
    const float* Wbp = (const float*)d_in[3];
    float* out = (float*)d_out;

    float *x36, *y0, *r0, *m1, *s, *w, *T, *WffP, *WfbP1, *WfbP2;
    double* part;
    cudaGetSymbolAddress((void**)&x36, g_x36);
    cudaGetSymbolAddress((void**)&y0, g_y0);
    cudaGetSymbolAddress((void**)&r0, g_r0);
    cudaGetSymbolAddress((void**)&m1, g_m1);
    cudaGetSymbolAddress((void**)&s,  g_s);
    cudaGetSymbolAddress((void**)&w,  g_w);
    cudaGetSymbolAddress((void**)&T,  g_T);
    cudaGetSymbolAddress((void**)&WffP,  g_WffP);
    cudaGetSymbolAddress((void**)&WfbP1, g_WfbP1);
    cudaGetSymbolAddress((void**)&WfbP2, g_WfbP2);
    cudaGetSymbolAddress((void**)&part, g_part);

    prep_kernel<<<256, 256>>>(x);
    wprep_kernel<<<64, 256>>>(Wff, Wfb);
    tgram_kernel<<<64, 128>>>(Wfb, T);

    // y0 = relu(conv3x3_pad1(x, W_ff)) -> padded (4,128,36,36)
    conv3a<64, 128, 1><<<dim3(16, 4, 8), 128>>>(x36, WffP, nullptr, nullptr,
                                                nullptr, y0);
    // r0 = x - A(pad(y0)) -> padded (4,64,36,36)
    conv3a<128, 64, 2><<<dim3(8, 4, 8), 128>>>(y0, WfbP1, x, nullptr,
                                               nullptr, r0);
    // m1 = M r0 via single 5x5 Gram conv
    conv5a<<<dim3(8, 4, 8), 128>>>(r0, T, m1);

    // Krylov Gram, scalar 500-step recursion, s = w0*r0 + w1*m1
    dots_kernel<<<NDOTCTA, 256>>>(r0, m1, part);
    recur_kernel<<<1, 32>>>(part, w);
    combine_kernel<<<128, 256>>>(r0, m1, w, s);

    // out = y0 + crop(A^T s) + conv1x1(x, W_bypass)
    conv3a<64, 128, 3><<<dim3(16, 4, 8), 128>>>(s, WfbP2, y0, x, Wbp, out);
}

// round 10
// speedup vs baseline: 3.5482x; 1.0840x over previous
#include <cuda_runtime.h>
#include <math.h>
#include <stdint.h>

constexpr float LRF = 0.001f;

// All feature maps stored 36x36 with logical origin (2,2); borders zero.
constexpr int NY36 = 4 * 128 * 36 * 36;
constexpr int NRP  = 4 * 64 * 36 * 36;
constexpr int NDOTCTA = 128;

__device__ __align__(16) float g_x36[NRP];
__device__ __align__(16) float g_y0[NY36];
__device__ __align__(16) float g_r0[NRP];
__device__ __align__(16) float g_m1[NRP];
__device__ __align__(16) float g_s[NRP];
__device__ __align__(16) float g_T[64 * 25 * 64];     // [(a*25+tap)*64 + b]
__device__ __align__(16) float g_WffP[64 * 9 * 128];  // [(ic*9+tap)*128 + oc]
__device__ __align__(16) float g_WfbP1[128 * 9 * 64]; // [(ic*9+tap)*64  + oc]
__device__ __align__(16) float g_WfbP2[64 * 9 * 128]; // [(ic*9+tap)*128 + og], flipped
__device__ double g_part[NDOTCTA * 3];

// ---------------- cp.async helpers ----------------
__device__ __forceinline__ void cpa16(uint32_t d, const void* s) {
    asm volatile("cp.async.cg.shared.global [%0], [%1], 16;" :: "r"(d), "l"(s));
}
__device__ __forceinline__ void cpcommit() { asm volatile("cp.async.commit_group;"); }
__device__ __forceinline__ void cpwait1()  { asm volatile("cp.async.wait_group 1;"); }
__device__ __forceinline__ void cpwait0()  { asm volatile("cp.async.wait_group 0;"); }

// ---------------------------------------------------------------------------
// setup: blocks 0..63 -> tgram (Gram 5x5 kernel of A A^T);
//        blocks 64..259 -> pad x to 36-wide, zero scratch, re-lay weights.
// ---------------------------------------------------------------------------
__global__ __launch_bounds__(256)
void setup_kernel(const float* __restrict__ x, const float* __restrict__ Wff,
                  const float* __restrict__ Wfb)
{
    __shared__ float red[64 * 25];
    if (blockIdx.x < 64) {
        const int b    = blockIdx.x;
        const int a    = threadIdx.x & 63;
        const int part = threadIdx.x >> 6;

        float acc[25];
        #pragma unroll
        for (int t = 0; t < 25; t++) acc[t] = 0.f;

        for (int o = part * 32; o < part * 32 + 32; o++) {
            float wbv[9], wav[9];
            #pragma unroll
            for (int i = 0; i < 9; i++) {
                wbv[i] = __ldg(Wfb + (o * 64 + b) * 9 + i);
                wav[i] = __ldg(Wfb + (o * 64 + a) * 9 + i);
            }
            #pragma unroll
            for (int du = -2; du <= 2; du++)
                #pragma unroll
                for (int dv = -2; dv <= 2; dv++) {
                    float s = 0.f;
                    #pragma unroll
                    for (int u = 0; u < 3; u++) {
                        if (u - du < 0 || u - du > 2) continue;
                        #pragma unroll
                        for (int v = 0; v < 3; v++) {
                            if (v - dv < 0 || v - dv > 2) continue;
                            s += wbv[u * 3 + v] * wav[(u - du) * 3 + (v - dv)];
                        }
                    }
                    acc[(du + 2) * 5 + (dv + 2)] += s;
                }
        }
        if (part == 3) {
            #pragma unroll
            for (int t = 0; t < 25; t++) red[a * 25 + t] = acc[t];
        }
        __syncthreads();
        if (part == 2) {
            #pragma unroll
            for (int t = 0; t < 25; t++) red[a * 25 + t] += acc[t];
        }
        __syncthreads();
        if (part == 1) {
            #pragma unroll
            for (int t = 0; t < 25; t++) red[a * 25 + t] += acc[t];
        }
        __syncthreads();
        if (part == 0) {
            #pragma unroll
            for (int t = 0; t < 25; t++)
                g_T[((size_t)a * 25 + t) * 64 + b] = acc[t] + red[a * 25 + t];
        }
    } else {
        const int i = (blockIdx.x - 64) * 256 + threadIdx.x;
        const int stride = 196 * 256;
        for (int j = i; j < NRP; j += stride) {
            int c36 = j % 36;
            int r36 = (j / 36) % 36;
            int nc  = j / 1296;
            float v = 0.f;
            if (r36 >= 2 && r36 < 34 && c36 >= 2 && c36 < 34)
                v = __ldg(x + nc * 1024 + (r36 - 2) * 32 + (c36 - 2));
            g_x36[j] = v;
            g_r0[j] = 0.f;
            g_m1[j] = 0.f;
        }
        for (int j = i; j < NY36; j += stride) g_y0[j] = 0.f;
        for (int j = i; j < 73728; j += stride) {
            int oc  = j % 128;
            int tap = (j / 128) % 9;
            int ic  = j / 1152;
            g_WffP[j]  = __ldg(Wff + (oc * 64 + ic) * 9 + tap);
            g_WfbP2[j] = __ldg(Wfb + (oc * 64 + ic) * 9 + (8 - tap));
        }
        for (int j = i; j < 73728; j += stride) {
            int oc  = j % 64;
            int tap = (j / 64) % 9;
            int ic  = j / 576;
            g_WfbP1[j] = __ldg(Wfb + (ic * 64 + oc) * 9 + tap);
        }
    }
}

// ---------------------------------------------------------------------------
// cp.async double-buffered 3x3 conv, OCB=4.  Block 128 = col(32) x ocg(4).
// CTA output: 4 rows x 16 oc.  Grid (OC/16, 4, 8).
// EPI: 1 relu -> padded out; 2 x - acc -> padded out;
//      3 y0 + acc + 1x1(x, wb) -> raw 32x32 out.
// ---------------------------------------------------------------------------
template<int IC, int OC, int EPI, int CH>
__global__ __launch_bounds__(128)
void conv3a(const float* __restrict__ in, const float* __restrict__ wgtP,
            const float* __restrict__ aux, const float* __restrict__ aux2,
            const float* __restrict__ wb, float* __restrict__ out)
{
    constexpr int NCH = IC / CH;
    constexpr int INF = CH * 6 * 36;
    constexpr int WF  = CH * 9 * 16;
    __shared__ __align__(16) float sbuf[2][INF + WF];
    __shared__ __align__(16) float wbs[(EPI == 3) ? 1024 : 4];

    const int ocblk = blockIdx.x;
    const int n     = blockIdx.y;
    const int R0    = blockIdx.z * 4;
    const int tid   = threadIdx.x;
    const int col   = tid & 31;
    const int ocg   = tid >> 5;

    if constexpr (EPI == 3) {
        for (int idx = tid; idx < 1024; idx += 128) {
            int o = idx & 15, c = idx >> 4;
            wbs[c * 16 + o] = __ldg(wb + (ocblk * 16 + o) * 64 + c);
        }
    }

    const float4* in4 = (const float4*)in;
    const float4* w4  = (const float4*)wgtP;

    auto stage = [&](int buf, int chunk) {
        uint32_t sb = (uint32_t)__cvta_generic_to_shared(&sbuf[buf][0]);
        #pragma unroll 1
        for (int idx = tid; idx < INF / 4; idx += 128) {
            int cc4 = idx % 9;
            int rr  = (idx / 9) % 6;
            int c   = idx / 54;
            cpa16(sb + idx * 16,
                  in4 + (((size_t)n * IC + chunk * CH + c) * 36 + R0 + 1 + rr) * 9 + cc4);
        }
        uint32_t wsb = sb + INF * 4;
        #pragma unroll 1
        for (int idx = tid; idx < WF / 4; idx += 128) {
            int f   = idx & 3;
            int tp  = (idx >> 2) % 9;
            int icl = idx / 36;
            cpa16(wsb + idx * 16,
                  w4 + ((((chunk * CH + icl) * 9 + tp) * OC + ocblk * 16) >> 2) + f);
        }
        cpcommit();
    };

    float acc[4][4] = {};

    stage(0, 0);
    for (int c = 0; c < NCH; c++) {
        if (c + 1 < NCH) { stage((c + 1) & 1, c + 1); cpwait1(); }
        else cpwait0();
        __syncthreads();
        const float* sb  = &sbuf[c & 1][0];
        const float* wsm = sb + INF;
        #pragma unroll
        for (int ch = 0; ch < CH; ch++) {
            float v[6][3];
            const float* sp = sb + ch * 216 + col + 1;
            #pragma unroll
            for (int rr = 0; rr < 6; rr++)
                #pragma unroll
                for (int cc = 0; cc < 3; cc++)
                    v[rr][cc] = sp[rr * 36 + cc];
            #pragma unroll
            for (int tap = 0; tap < 9; tap++) {
                int u = tap / 3, vv = tap % 3;
                float4 wv = *(const float4*)&wsm[(ch * 9 + tap) * 16 + ocg * 4];
                #pragma unroll
                for (int k = 0; k < 4; k++) {
                    acc[0][k] += v[u + k][vv] * wv.x;
                    acc[1][k] += v[u + k][vv] * wv.y;
                    acc[2][k] += v[u + k][vv] * wv.z;
                    acc[3][k] += v[u + k][vv] * wv.w;
                }
            }
        }
        __syncthreads();
    }

    float bp[4][4] = {};
    if constexpr (EPI == 3) {
        const float* xb = aux2 + ((size_t)n * 64 * 32 + R0) * 32 + col;
        #pragma unroll 4
        for (int c = 0; c < 64; c++) {
            float xv[4];
            #pragma unroll
            for (int k = 0; k < 4; k++) xv[k] = __ldg(xb + k * 32);
            float4 wv = *(const float4*)&wbs[c * 16 + ocg * 4];
            #pragma unroll
            for (int k = 0; k < 4; k++) {
                bp[0][k] += xv[k] * wv.x;
                bp[1][k] += xv[k] * wv.y;
                bp[2][k] += xv[k] * wv.z;
                bp[3][k] += xv[k] * wv.w;
            }
            xb += 1024;
        }
    }

    #pragma unroll
    for (int o = 0; o < 4; o++) {
        int og = ocblk * 16 + ocg * 4 + o;
        #pragma unroll
        for (int k = 0; k < 4; k++) {
            int row = R0 + k;
            float val = acc[o][k];
            if constexpr (EPI == 1) {
                val = fmaxf(val, 0.f);
                out[((size_t)(n * OC + og) * 36 + row + 2) * 36 + col + 2] = val;
            } else if constexpr (EPI == 2) {
                val = __ldg(aux + ((size_t)(n * OC + og) * 32 + row) * 32 + col) - val;
                out[((size_t)(n * OC + og) * 36 + row + 2) * 36 + col + 2] = val;
            } else {
                val = __ldg(aux + ((size_t)(n * 128 + og) * 36 + row + 2) * 36 + col + 2)
                      + val + bp[o][k];
                out[((size_t)(n * OC + og) * 32 + row) * 32 + col] = val;
            }
        }
    }
}

// ---------------------------------------------------------------------------
// cp.async double-buffered 5x5 Gram conv (M = A A^T), 64->64, OCB=4.
// Block 128 = col(32) x ocg(4); CTA = 4 rows x 16 oc.  Grid (4,4,8) = 128 CTAs.
// Fused Krylov dots: capture r0 center values from the staged chunk whose
// channels equal this warp's output channels; epilogue block-reduces
// <r0,r0>, <r0,m1>, <m1,m1> into partials[cta*3..].
// ---------------------------------------------------------------------------
__global__ __launch_bounds__(128)
void conv5a(const float* __restrict__ in, const float* __restrict__ T,
            float* __restrict__ out, double* __restrict__ partials)
{
    constexpr int CH  = 8, NCH = 8;
    constexpr int INF = CH * 8 * 36;   // 2304 floats
    constexpr int WF  = CH * 25 * 16;  // 3200 floats
    __shared__ __align__(16) float sbuf[2][INF + WF];

    const int ocblk = blockIdx.x;
    const int n     = blockIdx.y;
    const int R0    = blockIdx.z * 4;
    const int tid   = threadIdx.x;
    const int col   = tid & 31;
    const int ocg   = tid >> 5;
    const int cap_chunk = 2 * ocblk + (ocg >> 1);
    const int cap_base  = (ocg & 1) * 4;

    const float4* in4 = (const float4*)in;
    const float4* t4  = (const float4*)T;

    auto stage = [&](int buf, int chunk) {
        uint32_t sb = (uint32_t)__cvta_generic_to_shared(&sbuf[buf][0]);
        #pragma unroll 1
        for (int idx = tid; idx < INF / 4; idx += 128) {
            int cc4 = idx % 9;
            int rr  = (idx / 9) % 8;
            int c   = idx / 72;
            cpa16(sb + idx * 16,
                  in4 + (((size_t)n * 64 + chunk * CH + c) * 36 + R0 + rr) * 9 + cc4);
        }
        uint32_t wsb = sb + INF * 4;
        #pragma unroll 1
        for (int idx = tid; idx < WF / 4; idx += 128) {
            int f   = idx & 3;
            int tap = (idx >> 2) % 25;
            int al  = idx / 100;
            cpa16(wsb + idx * 16,
                  t4 + ((((chunk * CH + al) * 25 + tap) * 64 + ocblk * 16) >> 2) + f);
        }
        cpcommit();
    };

    float acc[4][4] = {};
    float rc[4][4];

    stage(0, 0);
    for (int c = 0; c < NCH; c++) {
        if (c + 1 < NCH) { stage((c + 1) & 1, c + 1); cpwait1(); }
        else cpwait0();
        __syncthreads();
        const float* sb  = &sbuf[c & 1][0];
        const float* wsm = sb + INF;
        if (c == cap_chunk) {
            #pragma unroll
            for (int o = 0; o < 4; o++)
                #pragma unroll
                for (int k = 0; k < 4; k++)
                    rc[o][k] = sb[(cap_base + o) * 288 + (k + 2) * 36 + col + 2];
        }
        #pragma unroll
        for (int ch = 0; ch < CH; ch++) {
            float v[8][5];
            const float* sp = sb + ch * 288 + col;
            #pragma unroll
            for (int rr = 0; rr < 8; rr++)
                #pragma unroll
                for (int dv = 0; dv < 5; dv++)
                    v[rr][dv] = sp[rr * 36 + dv];
            #pragma unroll
            for (int tap = 0; tap < 25; tap++) {
                int du = tap / 5, dv = tap % 5;
                float4 wv = *(const float4*)&wsm[(ch * 25 + tap) * 16 + ocg * 4];
                #pragma unroll
                for (int k = 0; k < 4; k++) {
                    acc[0][k] += v[k + du][dv] * wv.x;
                    acc[1][k] += v[k + du][dv] * wv.y;
                    acc[2][k] += v[k + du][dv] * wv.z;
                    acc[3][k] += v[k + du][dv] * wv.w;
                }
            }
        }
        __syncthreads();
    }

    #pragma unroll
    for (int o = 0; o < 4; o++) {
        int og = ocblk * 16 + ocg * 4 + o;
        #pragma unroll
        for (int k = 0; k < 4; k++)
            out[((size_t)(n * 64 + og) * 36 + R0 + k + 2) * 36 + col + 2] = acc[o][k];
    }

    // Fused dot products
    float l0 = 0.f, l1 = 0.f, l2 = 0.f;
    #pragma unroll
    for (int o = 0; o < 4; o++)
        #pragma unroll
        for (int k = 0; k < 4; k++) {
            l0 += rc[o][k] * rc[o][k];
            l1 += rc[o][k] * acc[o][k];
            l2 += acc[o][k] * acc[o][k];
        }
    __syncthreads();
    double* red = (double*)&sbuf[0][0];
    red[tid]       = (double)l0;
    red[128 + tid] = (double)l1;
    red[256 + tid] = (double)l2;
    __syncthreads();
    for (int s = 64; s > 0; s >>= 1) {
        if (tid < s) {
            red[tid]       += red[tid + s];
            red[128 + tid] += red[128 + tid + s];
            red[256 + tid] += red[256 + tid + s];
        }
        __syncthreads();
    }
    if (tid == 0) {
        int cta = blockIdx.x + 4 * blockIdx.y + 16 * blockIdx.z;
        partials[cta * 3 + 0] = red[0];
        partials[cta * 3 + 1] = red[128];
        partials[cta * 3 + 2] = red[256];
    }
}

// ---------------------------------------------------------------------------
// combine: reduce partials -> H, run blocked 500-step recursion (20 x 25
// steps with per-block-constant c), then s = w0*r0 + w1*m1.
// ---------------------------------------------------------------------------
__global__ __launch_bounds__(256)
void combine_kernel(const float* __restrict__ m0, const float* __restrict__ m1,
                    const double* __restrict__ partials, float* __restrict__ s)
{
    __shared__ double red[384];
    __shared__ float wsh[2];
    const int tid = threadIdx.x;
    if (tid < 128) {
        red[tid]       = partials[tid * 3 + 0];
        red[128 + tid] = partials[tid * 3 + 1];
        red[256 + tid] = partials[tid * 3 + 2];
    }
    __syncthreads();
    for (int st = 64; st > 0; st >>= 1) {
        if (tid < st) {
            red[tid]       += red[tid + st];
            red[128 + tid] += red[128 + tid + st];
            red[256 + tid] += red[256 + tid + st];
        }
        __syncthreads();
    }
    if (tid == 0) {
        const float H00 = (float)red[0], H01 = (float)red[128], H11 = (float)red[256];
        float p1 = 0.f, w0 = 0.f, w1 = 0.f;
        #pragma unroll
        for (int b = 0; b < 20; b++) {
            float nsq = H00 + p1 * (2.f * H01 + p1 * H11);
            float c = LRF * rsqrtf(nsq);
            w0 += 25.f * c;
            w1 += c * (25.f * p1 - c * 300.f);   // sum_{i<25} (p1 - i c)
            p1 -= 25.f * c;
        }
        wsh[0] = w0; wsh[1] = w1;
    }
    __syncthreads();
    const float w0 = wsh[0], w1 = wsh[1];

    const float4* a4 = (const float4*)m0;
    const float4* b4 = (const float4*)m1;
    float4* s4 = (float4*)s;
    for (int i = blockIdx.x * blockDim.x + tid; i < NRP / 4;
         i += gridDim.x * blockDim.x) {
        float4 a = __ldg(a4 + i), b = __ldg(b4 + i);
        float4 r;
        r.x = w0 * a.x + w1 * b.x;
        r.y = w0 * a.y + w1 * b.y;
        r.z = w0 * a.z + w1 * b.z;
        r.w = w0 * a.w + w1 * b.w;
        s4[i] = r;
    }
}

extern "C" void kernel_launch(void* const* d_in, const int* in_sizes, int n_in,
                              void* d_out, int out_size)
{
    const float* x   = (const float*)d_in[0];
    const float* Wff = (const float*)d_in[1];
    const float* Wfb = (const float*)d_in[2];
    const float* Wbp = (const float*)d_in[3];
    float* out = (float*)d_out;

    float *x36, *y0, *r0, *m1, *s, *T, *WffP, *WfbP1, *WfbP2;
    double* part;
    cudaGetSymbolAddress((void**)&x36, g_x36);
    cudaGetSymbolAddress((void**)&y0, g_y0);
    cudaGetSymbolAddress((void**)&r0, g_r0);
    cudaGetSymbolAddress((void**)&m1, g_m1);
    cudaGetSymbolAddress((void**)&s,  g_s);
    cudaGetSymbolAddress((void**)&T,  g_T);
    cudaGetSymbolAddress((void**)&WffP,  g_WffP);
    cudaGetSymbolAddress((void**)&WfbP1, g_WfbP1);
    cudaGetSymbolAddress((void**)&WfbP2, g_WfbP2);
    cudaGetSymbolAddress((void**)&part, g_part);

    // setup: tgram + padding + weight re-layout in one launch
    setup_kernel<<<260, 256>>>(x, Wff, Wfb);

    // y0 = relu(conv3x3_pad1(x, W_ff)) -> padded (4,128,36,36)
    conv3a<64, 128, 1, 16><<<dim3(8, 4, 8), 128>>>(x36, WffP, nullptr, nullptr,
                                                   nullptr, y0);
    // r0 = x - A(pad(y0)) -> padded (4,64,36,36)
    conv3a<128, 64, 2, 16><<<dim3(4, 4, 8), 128>>>(y0, WfbP1, x, nullptr,
                                                   nullptr, r0);
    // m1 = M r0 (5x5 Gram conv) + fused Krylov dots
    conv5a<<<dim3(4, 4, 8), 128>>>(r0, T, m1, part);

    // reduce + blocked 500-step recursion + s = w0*r0 + w1*m1
    combine_kernel<<<128, 256>>>(r0, m1, part, s);

    // out = y0 + crop(A^T s) + conv1x1(x, W_bypass)
    conv3a<64, 128, 3, 8><<<dim3(8, 4, 8), 128>>>(s, WfbP2, y0, x, Wbp, out);
}

// round 11
// speedup vs baseline: 4.7481x; 1.3382x over previous
#include <cuda_runtime.h>
#include <math.h>
#include <stdint.h>

constexpr float LRF = 0.001f;

// All feature maps stored 36x36 with logical origin (2,2); borders zero.
constexpr int NY36 = 4 * 128 * 36 * 36;
constexpr int NRP  = 4 * 64 * 36 * 36;
constexpr int NDOTCTA = 256;

__device__ __align__(16) float g_x36[NRP];
__device__ __align__(16) float g_y0[NY36];
__device__ __align__(16) float g_r0[NRP];
__device__ __align__(16) float g_m1[NRP];
__device__ __align__(16) float g_s[NRP];
__device__ __align__(16) float g_T[64 * 25 * 64];     // [(a*25+tap)*64 + b]
__device__ __align__(16) float g_WffP[64 * 9 * 128];  // [(ic*9+tap)*128 + oc]
__device__ __align__(16) float g_WfbP1[128 * 9 * 64]; // [(ic*9+tap)*64  + oc]
__device__ __align__(16) float g_WfbP2[64 * 9 * 128]; // [(ic*9+tap)*128 + og], flipped
__device__ double g_part[NDOTCTA * 3];

// ---------------- cp.async helpers ----------------
__device__ __forceinline__ void cpa16(uint32_t d, const void* s) {
    asm volatile("cp.async.cg.shared.global [%0], [%1], 16;" :: "r"(d), "l"(s));
}
__device__ __forceinline__ void cpcommit() { asm volatile("cp.async.commit_group;"); }
__device__ __forceinline__ void cpwait1()  { asm volatile("cp.async.wait_group 1;"); }
__device__ __forceinline__ void cpwait0()  { asm volatile("cp.async.wait_group 0;"); }

// ---------------------------------------------------------------------------
// setup: blocks 0..63 -> tgram (Gram 5x5 kernel of A A^T);
//        blocks 64..259 -> pad x to 36-wide, zero scratch, re-lay weights.
// ---------------------------------------------------------------------------
__global__ __launch_bounds__(256)
void setup_kernel(const float* __restrict__ x, const float* __restrict__ Wff,
                  const float* __restrict__ Wfb)
{
    __shared__ float red[64 * 25];
    if (blockIdx.x < 64) {
        const int b    = blockIdx.x;
        const int a    = threadIdx.x & 63;
        const int part = threadIdx.x >> 6;

        float acc[25];
        #pragma unroll
        for (int t = 0; t < 25; t++) acc[t] = 0.f;

        for (int o = part * 32; o < part * 32 + 32; o++) {
            float wbv[9], wav[9];
            #pragma unroll
            for (int i = 0; i < 9; i++) {
                wbv[i] = __ldg(Wfb + (o * 64 + b) * 9 + i);
                wav[i] = __ldg(Wfb + (o * 64 + a) * 9 + i);
            }
            #pragma unroll
            for (int du = -2; du <= 2; du++)
                #pragma unroll
                for (int dv = -2; dv <= 2; dv++) {
                    float s = 0.f;
                    #pragma unroll
                    for (int u = 0; u < 3; u++) {
                        if (u - du < 0 || u - du > 2) continue;
                        #pragma unroll
                        for (int v = 0; v < 3; v++) {
                            if (v - dv < 0 || v - dv > 2) continue;
                            s += wbv[u * 3 + v] * wav[(u - du) * 3 + (v - dv)];
                        }
                    }
                    acc[(du + 2) * 5 + (dv + 2)] += s;
                }
        }
        if (part == 3) {
            #pragma unroll
            for (int t = 0; t < 25; t++) red[a * 25 + t] = acc[t];
        }
        __syncthreads();
        if (part == 2) {
            #pragma unroll
            for (int t = 0; t < 25; t++) red[a * 25 + t] += acc[t];
        }
        __syncthreads();
        if (part == 1) {
            #pragma unroll
            for (int t = 0; t < 25; t++) red[a * 25 + t] += acc[t];
        }
        __syncthreads();
        if (part == 0) {
            #pragma unroll
            for (int t = 0; t < 25; t++)
                g_T[((size_t)a * 25 + t) * 64 + b] = acc[t] + red[a * 25 + t];
        }
    } else {
        const int i = (blockIdx.x - 64) * 256 + threadIdx.x;
        const int stride = 196 * 256;
        for (int j = i; j < NRP; j += stride) {
            int c36 = j % 36;
            int r36 = (j / 36) % 36;
            int nc  = j / 1296;
            float v = 0.f;
            if (r36 >= 2 && r36 < 34 && c36 >= 2 && c36 < 34)
                v = __ldg(x + nc * 1024 + (r36 - 2) * 32 + (c36 - 2));
            g_x36[j] = v;
            g_r0[j] = 0.f;
            g_m1[j] = 0.f;
        }
        for (int j = i; j < NY36; j += stride) g_y0[j] = 0.f;
        for (int j = i; j < 73728; j += stride) {
            int oc  = j % 128;
            int tap = (j / 128) % 9;
            int ic  = j / 1152;
            g_WffP[j]  = __ldg(Wff + (oc * 64 + ic) * 9 + tap);
            g_WfbP2[j] = __ldg(Wfb + (oc * 64 + ic) * 9 + (8 - tap));
        }
        for (int j = i; j < 73728; j += stride) {
            int oc  = j % 64;
            int tap = (j / 64) % 9;
            int ic  = j / 576;
            g_WfbP1[j] = __ldg(Wfb + (ic * 64 + oc) * 9 + tap);
        }
    }
}

// ---------------------------------------------------------------------------
// cp.async double-buffered 3x3 conv.  Block 128 = col(32) x ocg(4),
// OCB = OCTOT/4 oc per thread.  CTA output: 4 rows x OCTOT oc.
// Grid (OC/OCTOT, 4, 8)  -- always >= 256 CTAs.
// EPI: 1 relu -> padded out; 2 x - acc -> padded out;
//      3 y0 + acc + 1x1(x, wb) -> raw 32x32 out.
// ---------------------------------------------------------------------------
template<int IC, int OC, int EPI, int CH, int OCTOT>
__global__ __launch_bounds__(128)
void conv3a(const float* __restrict__ in, const float* __restrict__ wgtP,
            const float* __restrict__ aux, const float* __restrict__ aux2,
            const float* __restrict__ wb, float* __restrict__ out)
{
    constexpr int NCH = IC / CH;
    constexpr int OCB = OCTOT / 4;
    constexpr int WPT = OCTOT / 4;           // float4s per tap row
    constexpr int INF = CH * 6 * 36;
    constexpr int WF  = CH * 9 * OCTOT;
    __shared__ __align__(16) float sbuf[2][INF + WF];
    __shared__ __align__(16) float wbs[(EPI == 3) ? 64 * OCTOT : 4];

    const int ocblk = blockIdx.x;
    const int n     = blockIdx.y;
    const int R0    = blockIdx.z * 4;
    const int tid   = threadIdx.x;
    const int col   = tid & 31;
    const int ocg   = tid >> 5;

    if constexpr (EPI == 3) {
        for (int idx = tid; idx < 64 * OCTOT; idx += 128) {
            int o = idx % OCTOT, c = idx / OCTOT;
            wbs[c * OCTOT + o] = __ldg(wb + (ocblk * OCTOT + o) * 64 + c);
        }
    }

    const float4* in4 = (const float4*)in;
    const float4* w4  = (const float4*)wgtP;

    auto stage = [&](int buf, int chunk) {
        uint32_t sb = (uint32_t)__cvta_generic_to_shared(&sbuf[buf][0]);
        #pragma unroll 1
        for (int idx = tid; idx < INF / 4; idx += 128) {
            int cc4 = idx % 9;
            int rr  = (idx / 9) % 6;
            int c   = idx / 54;
            cpa16(sb + idx * 16,
                  in4 + (((size_t)n * IC + chunk * CH + c) * 36 + R0 + 1 + rr) * 9 + cc4);
        }
        uint32_t wsb = sb + INF * 4;
        #pragma unroll 1
        for (int idx = tid; idx < WF / 4; idx += 128) {
            int f   = idx % WPT;
            int tp  = (idx / WPT) % 9;
            int icl = idx / (9 * WPT);
            cpa16(wsb + idx * 16,
                  w4 + ((((chunk * CH + icl) * 9 + tp) * OC + ocblk * OCTOT) >> 2) + f);
        }
        cpcommit();
    };

    float acc[OCB][4] = {};

    stage(0, 0);
    for (int c = 0; c < NCH; c++) {
        if (c + 1 < NCH) { stage((c + 1) & 1, c + 1); cpwait1(); }
        else cpwait0();
        __syncthreads();
        const float* sb  = &sbuf[c & 1][0];
        const float* wsm = sb + INF;
        #pragma unroll
        for (int ch = 0; ch < CH; ch++) {
            float v[6][3];
            const float* sp = sb + ch * 216 + col + 1;
            #pragma unroll
            for (int rr = 0; rr < 6; rr++)
                #pragma unroll
                for (int cc = 0; cc < 3; cc++)
                    v[rr][cc] = sp[rr * 36 + cc];
            #pragma unroll
            for (int tap = 0; tap < 9; tap++) {
                int u = tap / 3, vv = tap % 3;
                const float* wp = &wsm[(ch * 9 + tap) * OCTOT + ocg * OCB];
                if constexpr (OCB == 4) {
                    float4 wv = *(const float4*)wp;
                    #pragma unroll
                    for (int k = 0; k < 4; k++) {
                        acc[0][k] += v[u + k][vv] * wv.x;
                        acc[1][k] += v[u + k][vv] * wv.y;
                        acc[2][k] += v[u + k][vv] * wv.z;
                        acc[3][k] += v[u + k][vv] * wv.w;
                    }
                } else {
                    float2 wv = *(const float2*)wp;
                    #pragma unroll
                    for (int k = 0; k < 4; k++) {
                        acc[0][k] += v[u + k][vv] * wv.x;
                        acc[1][k] += v[u + k][vv] * wv.y;
                    }
                }
            }
        }
        __syncthreads();
    }

    float bp[OCB][4] = {};
    if constexpr (EPI == 3) {
        const float* xb = aux2 + ((size_t)n * 64 * 32 + R0) * 32 + col;
        #pragma unroll 4
        for (int c = 0; c < 64; c++) {
            float xv[4];
            #pragma unroll
            for (int k = 0; k < 4; k++) xv[k] = __ldg(xb + k * 32);
            const float* wp = &wbs[c * OCTOT + ocg * OCB];
            #pragma unroll
            for (int o = 0; o < OCB; o++) {
                float wv = wp[o];
                #pragma unroll
                for (int k = 0; k < 4; k++) bp[o][k] += xv[k] * wv;
            }
            xb += 1024;
        }
    }

    #pragma unroll
    for (int o = 0; o < OCB; o++) {
        int og = ocblk * OCTOT + ocg * OCB + o;
        #pragma unroll
        for (int k = 0; k < 4; k++) {
            int row = R0 + k;
            float val = acc[o][k];
            if constexpr (EPI == 1) {
                val = fmaxf(val, 0.f);
                out[((size_t)(n * OC + og) * 36 + row + 2) * 36 + col + 2] = val;
            } else if constexpr (EPI == 2) {
                val = __ldg(aux + ((size_t)(n * OC + og) * 32 + row) * 32 + col) - val;
                out[((size_t)(n * OC + og) * 36 + row + 2) * 36 + col + 2] = val;
            } else {
                val = __ldg(aux + ((size_t)(n * 128 + og) * 36 + row + 2) * 36 + col + 2)
                      + val + bp[o][k];
                out[((size_t)(n * OC + og) * 32 + row) * 32 + col] = val;
            }
        }
    }
}

// ---------------------------------------------------------------------------
// cp.async double-buffered 5x5 Gram conv (M = A A^T), 64->64, OCB=2.
// Block 128 = col(32) x ocg(4); CTA = 4 rows x 8 oc.  Grid (8,4,8) = 256 CTAs.
// Fused Krylov dots: CTA's 8 output channels == staged chunk `ocblk`'s input
// channels; capture r0 centers there, block-reduce <r0,r0>,<r0,m1>,<m1,m1>.
// ---------------------------------------------------------------------------
__global__ __launch_bounds__(128)
void conv5a(const float* __restrict__ in, const float* __restrict__ T,
            float* __restrict__ out, double* __restrict__ partials)
{
    constexpr int CH  = 8, NCH = 8;
    constexpr int INF = CH * 8 * 36;   // 2304 floats
    constexpr int WF  = CH * 25 * 8;   // 1600 floats
    __shared__ __align__(16) float sbuf[2][INF + WF];

    const int ocblk = blockIdx.x;
    const int n     = blockIdx.y;
    const int R0    = blockIdx.z * 4;
    const int tid   = threadIdx.x;
    const int col   = tid & 31;
    const int ocg   = tid >> 5;
    const int cap_base = ocg * 2;

    const float4* in4 = (const float4*)in;
    const float4* t4  = (const float4*)T;

    auto stage = [&](int buf, int chunk) {
        uint32_t sb = (uint32_t)__cvta_generic_to_shared(&sbuf[buf][0]);
        #pragma unroll 1
        for (int idx = tid; idx < INF / 4; idx += 128) {
            int cc4 = idx % 9;
            int rr  = (idx / 9) % 8;
            int c   = idx / 72;
            cpa16(sb + idx * 16,
                  in4 + (((size_t)n * 64 + chunk * CH + c) * 36 + R0 + rr) * 9 + cc4);
        }
        uint32_t wsb = sb + INF * 4;
        #pragma unroll 1
        for (int idx = tid; idx < WF / 4; idx += 128) {
            int f   = idx & 1;
            int tap = (idx >> 1) % 25;
            int al  = idx / 50;
            cpa16(wsb + idx * 16,
                  t4 + ((((chunk * CH + al) * 25 + tap) * 64 + ocblk * 8) >> 2) + f);
        }
        cpcommit();
    };

    float acc[2][4] = {};
    float rc[2][4];

    stage(0, 0);
    for (int c = 0; c < NCH; c++) {
        if (c + 1 < NCH) { stage((c + 1) & 1, c + 1); cpwait1(); }
        else cpwait0();
        __syncthreads();
        const float* sb  = &sbuf[c & 1][0];
        const float* wsm = sb + INF;
        if (c == ocblk) {
            #pragma unroll
            for (int o = 0; o < 2; o++)
                #pragma unroll
                for (int k = 0; k < 4; k++)
                    rc[o][k] = sb[(cap_base + o) * 288 + (k + 2) * 36 + col + 2];
        }
        #pragma unroll
        for (int ch = 0; ch < CH; ch++) {
            float v[8][5];
            const float* sp = sb + ch * 288 + col;
            #pragma unroll
            for (int rr = 0; rr < 8; rr++)
                #pragma unroll
                for (int dv = 0; dv < 5; dv++)
                    v[rr][dv] = sp[rr * 36 + dv];
            #pragma unroll
            for (int tap = 0; tap < 25; tap++) {
                int du = tap / 5, dv = tap % 5;
                float2 wv = *(const float2*)&wsm[(ch * 25 + tap) * 8 + ocg * 2];
                #pragma unroll
                for (int k = 0; k < 4; k++) {
                    acc[0][k] += v[k + du][dv] * wv.x;
                    acc[1][k] += v[k + du][dv] * wv.y;
                }
            }
        }
        __syncthreads();
    }

    #pragma unroll
    for (int o = 0; o < 2; o++) {
        int og = ocblk * 8 + ocg * 2 + o;
        #pragma unroll
        for (int k = 0; k < 4; k++)
            out[((size_t)(n * 64 + og) * 36 + R0 + k + 2) * 36 + col + 2] = acc[o][k];
    }

    // Fused dot products
    float l0 = 0.f, l1 = 0.f, l2 = 0.f;
    #pragma unroll
    for (int o = 0; o < 2; o++)
        #pragma unroll
        for (int k = 0; k < 4; k++) {
            l0 += rc[o][k] * rc[o][k];
            l1 += rc[o][k] * acc[o][k];
            l2 += acc[o][k] * acc[o][k];
        }
    __syncthreads();
    double* red = (double*)&sbuf[0][0];
    red[tid]       = (double)l0;
    red[128 + tid] = (double)l1;
    red[256 + tid] = (double)l2;
    __syncthreads();
    for (int s = 64; s > 0; s >>= 1) {
        if (tid < s) {
            red[tid]       += red[tid + s];
            red[128 + tid] += red[128 + tid + s];
            red[256 + tid] += red[256 + tid + s];
        }
        __syncthreads();
    }
    if (tid == 0) {
        int cta = blockIdx.x + 8 * blockIdx.y + 32 * blockIdx.z;
        partials[cta * 3 + 0] = red[0];
        partials[cta * 3 + 1] = red[128];
        partials[cta * 3 + 2] = red[256];
    }
}

// ---------------------------------------------------------------------------
// combine: reduce partials -> H, blocked 500-step recursion (20 x 25 steps),
// then s = w0*r0 + w1*m1.
// ---------------------------------------------------------------------------
__global__ __launch_bounds__(256)
void combine_kernel(const float* __restrict__ m0, const float* __restrict__ m1,
                    const double* __restrict__ partials, float* __restrict__ s)
{
    __shared__ double red[768];
    __shared__ float wsh[2];
    const int tid = threadIdx.x;
    red[tid]       = partials[tid * 3 + 0];
    red[256 + tid] = partials[tid * 3 + 1];
    red[512 + tid] = partials[tid * 3 + 2];
    __syncthreads();
    for (int st = 128; st > 0; st >>= 1) {
        if (tid < st) {
            red[tid]       += red[tid + st];
            red[256 + tid] += red[256 + tid + st];
            red[512 + tid] += red[512 + tid + st];
        }
        __syncthreads();
    }
    if (tid == 0) {
        const float H00 = (float)red[0], H01 = (float)red[256], H11 = (float)red[512];
        float p1 = 0.f, w0 = 0.f, w1 = 0.f;
        #pragma unroll
        for (int b = 0; b < 20; b++) {
            float nsq = H00 + p1 * (2.f * H01 + p1 * H11);
            float c = LRF * rsqrtf(nsq);
            w0 += 25.f * c;
            w1 += c * (25.f * p1 - c * 300.f);   // sum_{i<25} (p1 - i c)
            p1 -= 25.f * c;
        }
        wsh[0] = w0; wsh[1] = w1;
    }
    __syncthreads();
    const float w0 = wsh[0], w1 = wsh[1];

    const float4* a4 = (const float4*)m0;
    const float4* b4 = (const float4*)m1;
    float4* s4 = (float4*)s;
    for (int i = blockIdx.x * blockDim.x + tid; i < NRP / 4;
         i += gridDim.x * blockDim.x) {
        float4 a = __ldg(a4 + i), b = __ldg(b4 + i);
        float4 r;
        r.x = w0 * a.x + w1 * b.x;
        r.y = w0 * a.y + w1 * b.y;
        r.z = w0 * a.z + w1 * b.z;
        r.w = w0 * a.w + w1 * b.w;
        s4[i] = r;
    }
}

extern "C" void kernel_launch(void* const* d_in, const int* in_sizes, int n_in,
                              void* d_out, int out_size)
{
    const float* x   = (const float*)d_in[0];
    const float* Wff = (const float*)d_in[1];
    const float* Wfb = (const float*)d_in[2];
    const float* Wbp = (const float*)d_in[3];
    float* out = (float*)d_out;

    float *x36, *y0, *r0, *m1, *s, *T, *WffP, *WfbP1, *WfbP2;
    double* part;
    cudaGetSymbolAddress((void**)&x36, g_x36);
    cudaGetSymbolAddress((void**)&y0, g_y0);
    cudaGetSymbolAddress((void**)&r0, g_r0);
    cudaGetSymbolAddress((void**)&m1, g_m1);
    cudaGetSymbolAddress((void**)&s,  g_s);
    cudaGetSymbolAddress((void**)&T,  g_T);
    cudaGetSymbolAddress((void**)&WffP,  g_WffP);
    cudaGetSymbolAddress((void**)&WfbP1, g_WfbP1);
    cudaGetSymbolAddress((void**)&WfbP2, g_WfbP2);
    cudaGetSymbolAddress((void**)&part, g_part);

    // setup: tgram + padding + weight re-layout in one launch
    setup_kernel<<<260, 256>>>(x, Wff, Wfb);

    // y0 = relu(conv3x3_pad1(x, W_ff)) -> padded (4,128,36,36)   [256 CTAs]
    conv3a<64, 128, 1, 16, 16><<<dim3(8, 4, 8), 128>>>(x36, WffP, nullptr,
                                                       nullptr, nullptr, y0);
    // r0 = x - A(pad(y0)) -> padded (4,64,36,36)                 [256 CTAs]
    conv3a<128, 64, 2, 16, 8><<<dim3(8, 4, 8), 128>>>(y0, WfbP1, x, nullptr,
                                                      nullptr, r0);
    // m1 = M r0 (5x5 Gram conv) + fused Krylov dots              [256 CTAs]
    conv5a<<<dim3(8, 4, 8), 128>>>(r0, T, m1, part);

    // reduce + blocked 500-step recursion + s = w0*r0 + w1*m1
    combine_kernel<<<128, 256>>>(r0, m1, part, s);

    // out = y0 + crop(A^T s) + conv1x1(x, W_bypass)              [256 CTAs]
    conv3a<64, 128, 3, 8, 16><<<dim3(8, 4, 8), 128>>>(s, WfbP2, y0, x, Wbp, out);
}